// round 1
// baseline (speedup 1.0000x reference)
#include <cuda_runtime.h>
#include <cuda_bf16.h>
#include <math.h>

// Problem constants
#define BATCH 8
#define PTS   2048
#define NPTS  (BATCH*PTS)      // 16384
#define KNN   20
#define NEDGE (NPTS*KNN)       // 327680

// ---------------- scratch (static device globals; no allocations) ----------------
__device__ float g_x0[NPTS*6];
__device__ float g_h [NPTS*192];    // x1 | x2 | x3 concatenated
__device__ float g_xsq[NPTS];
__device__ int   g_knn[NEDGE];
__device__ float g_T [NEDGE*64];    // hidden after first edge-MLP linear (relu'd)
__device__ float g_Y [NEDGE*64];    // after second edge-MLP linear (pre-max)
__device__ float g_t1[NPTS*1024];
__device__ float g_t2[NPTS*256];
__device__ float g_t3[NPTS*128];

// ---------------- build x0 = [feats | pos] ----------------
__global__ void x0_kernel(const float* __restrict__ feats, const float* __restrict__ pos) {
    int p = blockIdx.x * 256 + threadIdx.x;
    if (p >= NPTS) return;
    g_x0[p*6+0] = feats[p*3+0];
    g_x0[p*6+1] = feats[p*3+1];
    g_x0[p*6+2] = feats[p*3+2];
    g_x0[p*6+3] = pos[p*3+0];
    g_x0[p*6+4] = pos[p*3+1];
    g_x0[p*6+5] = pos[p*3+2];
}

// ---------------- squared norms ----------------
template<int D>
__global__ void xsq_kernel(const float* __restrict__ X, int stride, int off) {
    int p = blockIdx.x * 256 + threadIdx.x;
    if (p >= NPTS) return;
    float s = 0.f;
    #pragma unroll
    for (int f = 0; f < D; f++) {
        float v = X[(size_t)p*stride + off + f];
        s += v*v;
    }
    g_xsq[p] = s;
}

// ---------------- kNN: one thread per query point ----------------
template<int D>
__global__ void knn_kernel(const float* __restrict__ X, int stride, int off) {
    const int T = 128;
    __shared__ float cf[T*D];
    __shared__ float cn[T];
    int tid = threadIdx.x;
    int b   = blockIdx.y;
    int p   = b*PTS + blockIdx.x*256 + tid;

    float xi[D];
    #pragma unroll
    for (int f = 0; f < D; f++) xi[f] = X[(size_t)p*stride + off + f];
    float xin = g_xsq[p];

    float d[KNN];
    int   id[KNN];
    #pragma unroll
    for (int k = 0; k < KNN; k++) { d[k] = 3.4e38f; id[k] = 0; }
    float worst = 3.4e38f;

    for (int t0 = 0; t0 < PTS; t0 += T) {
        int q0 = b*PTS + t0;
        __syncthreads();
        if (D % 4 == 0) {
            for (int u = tid; u < T*D/4; u += 256) {
                int c  = u / (D/4);
                int fv = u % (D/4);
                *(float4*)&cf[c*D + fv*4] =
                    *(const float4*)&X[(size_t)(q0+c)*stride + off + fv*4];
            }
        } else {
            for (int u = tid; u < T*D; u += 256) {
                int c = u / D, f = u % D;
                cf[c*D + f] = X[(size_t)(q0+c)*stride + off + f];
            }
        }
        if (tid < T) cn[tid] = g_xsq[q0 + tid];
        __syncthreads();

        for (int c = 0; c < T; c++) {
            float dot;
            if (D % 4 == 0) {
                float d0=0.f,d1=0.f,d2=0.f,d3=0.f;
                #pragma unroll
                for (int f = 0; f < D; f += 4) {
                    float4 v = *(float4*)&cf[c*D + f];
                    d0 += xi[f+0]*v.x; d1 += xi[f+1]*v.y;
                    d2 += xi[f+2]*v.z; d3 += xi[f+3]*v.w;
                }
                dot = (d0+d1) + (d2+d3);
            } else {
                dot = 0.f;
                #pragma unroll
                for (int f = 0; f < D; f++) dot += xi[f]*cf[c*D + f];
            }
            float dist = xin + cn[c] - 2.f*dot;
            if (dist < worst) {
                int pos = KNN-1;
                while (pos > 0 && d[pos-1] > dist) {
                    d[pos] = d[pos-1]; id[pos] = id[pos-1]; pos--;
                }
                d[pos] = dist; id[pos] = q0 + c;
                worst = d[KNN-1];
            }
        }
    }
    #pragma unroll
    for (int k = 0; k < KNN; k++) g_knn[(size_t)p*KNN + k] = id[k];
}

// ---------------- tiled fp32 GEMM: C[M,N] = act(A @ W + b) ----------------
// MODE 0 (PLAIN): A is row-major [M, lda-strided], use columns [0,Kd)
// MODE 1 (GATHER): A row r is the edge feature of edge r: p=r/KNN, j=knn[r],
//                  feature f<D -> x_p[f], f>=D -> x_j[f-D]-x_p[f-D]
#define GEMM_BM 64
#define GEMM_BN 64
#define GEMM_BK 16

template<int MODE, int D>
__global__ void gemm_kernel(const float* __restrict__ A, int lda, int aoff,
                            const float* __restrict__ W,
                            const float* __restrict__ bias,
                            float* __restrict__ C,
                            int M, int N, int Kd, int do_relu) {
    __shared__ float As[GEMM_BK][GEMM_BM + 4];
    __shared__ float Ws[GEMM_BK][GEMM_BN];

    int t  = threadIdx.x;           // 256 threads
    int m0 = blockIdx.x * GEMM_BM;
    int n0 = blockIdx.y * GEMM_BN;
    int tx = t & 15, ty = t >> 4;

    float acc[4][4];
    #pragma unroll
    for (int i = 0; i < 4; i++)
        #pragma unroll
        for (int j = 0; j < 4; j++) acc[i][j] = 0.f;

    // A tile loader indices
    int arow_g = t & 63;           // gather mode: row within tile
    int acg    = (t >> 6) << 2;    // gather mode: col group base
    int arow_p = t >> 2;           // plain mode: row within tile
    int acp    = (t & 3) << 2;     // plain mode: 4 consecutive cols
    // W loader
    int wk = t >> 4;               // 0..15
    int wn = (t & 15) << 2;

    int p = 0, j = 0;
    if (MODE == 1) {
        int r = m0 + arow_g;
        p = r / KNN;
        j = g_knn[r];
    }

    for (int kk = 0; kk < Kd; kk += GEMM_BK) {
        if (MODE == 0) {
            int r = m0 + arow_p;
            #pragma unroll
            for (int c = 0; c < 4; c++) {
                int f = kk + acp + c;
                As[acp + c][arow_p] = (f < Kd) ? A[(size_t)r*lda + f] : 0.f;
            }
        } else {
            #pragma unroll
            for (int c = 0; c < 4; c++) {
                int f = kk + acg + c;
                float v = 0.f;
                if (f < Kd) {
                    if (f < D) {
                        v = A[(size_t)p*lda + aoff + f];
                    } else {
                        int ff = f - D;
                        v = A[(size_t)j*lda + aoff + ff] - A[(size_t)p*lda + aoff + ff];
                    }
                }
                As[acg + c][arow_g] = v;
            }
        }
        {
            int krow = kk + wk;
            float4 wv = make_float4(0.f,0.f,0.f,0.f);
            if (krow < Kd) wv = *(const float4*)&W[(size_t)krow*N + n0 + wn];
            *(float4*)&Ws[wk][wn] = wv;
        }
        __syncthreads();
        #pragma unroll
        for (int k = 0; k < GEMM_BK; k++) {
            float4 av = *(float4*)&As[k][ty << 2];
            float4 wv = *(float4*)&Ws[k][tx << 2];
            float a_[4] = {av.x, av.y, av.z, av.w};
            float w_[4] = {wv.x, wv.y, wv.z, wv.w};
            #pragma unroll
            for (int i = 0; i < 4; i++)
                #pragma unroll
                for (int jj = 0; jj < 4; jj++)
                    acc[i][jj] += a_[i] * w_[jj];
        }
        __syncthreads();
    }

    #pragma unroll
    for (int i = 0; i < 4; i++) {
        int m = m0 + (ty << 2) + i;
        int n = n0 + (tx << 2);
        float4 out;
        float* o = (float*)&out;
        #pragma unroll
        for (int jj = 0; jj < 4; jj++) {
            float v = acc[i][jj] + bias[n + jj];
            if (do_relu) v = fmaxf(v, 0.f);
            o[jj] = v;
        }
        *(float4*)&C[(size_t)m*N + n] = out;
    }
}

// ---------------- max over K neighbors, write into concat buffer ----------------
__global__ void maxred_kernel(const float* __restrict__ Y, int off) {
    int t = blockIdx.x * 256 + threadIdx.x;
    if (t >= NPTS*64) return;
    int p = t >> 6, c = t & 63;
    float m = -3.4e38f;
    #pragma unroll
    for (int k = 0; k < KNN; k++)
        m = fmaxf(m, Y[((size_t)p*KNN + k)*64 + c]);
    g_h[(size_t)p*192 + off + c] = m;
}

// ---------------- head final: 128->13 + log_softmax (warp per point) ----------------
__global__ void head4_kernel(const float* __restrict__ W,
                             const float* __restrict__ bias,
                             float* __restrict__ out) {
    int gt   = blockIdx.x * 256 + threadIdx.x;
    int warp = gt >> 5;
    int lane = threadIdx.x & 31;
    if (warp >= NPTS) return;
    float o = -3.4e38f;
    if (lane < 13) {
        float s = bias[lane];
        #pragma unroll 8
        for (int c = 0; c < 128; c++)
            s += g_t3[(size_t)warp*128 + c] * W[c*13 + lane];
        o = s;
    }
    float m = o;
    #pragma unroll
    for (int d = 16; d; d >>= 1) m = fmaxf(m, __shfl_xor_sync(0xffffffffu, m, d));
    float e = (lane < 13) ? expf(o - m) : 0.f;
    float ssum = e;
    #pragma unroll
    for (int d = 16; d; d >>= 1) ssum += __shfl_xor_sync(0xffffffffu, ssum, d);
    if (lane < 13) out[(size_t)warp*13 + lane] = o - m - logf(ssum);
}

// ---------------- host ----------------
static inline void run_gemm_plain(const float* A, int lda, const float* W,
                                  const float* b, float* C,
                                  int M, int N, int Kd, int relu) {
    dim3 grid(M/GEMM_BM, N/GEMM_BN);
    gemm_kernel<0,0><<<grid, 256>>>(A, lda, 0, W, b, C, M, N, Kd, relu);
}

extern "C" void kernel_launch(void* const* d_in, const int* in_sizes, int n_in,
                              void* d_out, int out_size) {
    const float* feats = (const float*)d_in[0];
    const float* pos   = (const float*)d_in[1];
    // d_in[2] = batch (structure known: contiguous, equal sized)
    const float* w1a = (const float*)d_in[3];
    const float* b1a = (const float*)d_in[4];
    const float* w1b = (const float*)d_in[5];
    const float* b1b = (const float*)d_in[6];
    const float* w2a = (const float*)d_in[7];
    const float* b2a = (const float*)d_in[8];
    const float* w2b = (const float*)d_in[9];
    const float* b2b = (const float*)d_in[10];
    const float* w3a = (const float*)d_in[11];
    const float* b3a = (const float*)d_in[12];
    const float* w3b = (const float*)d_in[13];
    const float* b3b = (const float*)d_in[14];
    const float* hw1 = (const float*)d_in[15];
    const float* hb1 = (const float*)d_in[16];
    const float* hw2 = (const float*)d_in[17];
    const float* hb2 = (const float*)d_in[18];
    const float* hw3 = (const float*)d_in[19];
    const float* hb3 = (const float*)d_in[20];
    const float* hw4 = (const float*)d_in[21];
    const float* hb4 = (const float*)d_in[22];
    float* out = (float*)d_out;

    float *x0, *h, *T, *Y, *t1, *t2;
    cudaGetSymbolAddress((void**)&x0, g_x0);
    cudaGetSymbolAddress((void**)&h,  g_h);
    cudaGetSymbolAddress((void**)&T,  g_T);
    cudaGetSymbolAddress((void**)&Y,  g_Y);
    cudaGetSymbolAddress((void**)&t1, g_t1);
    cudaGetSymbolAddress((void**)&t2, g_t2);
    float* t3; cudaGetSymbolAddress((void**)&t3, g_t3);

    dim3 knn_grid(PTS/256, BATCH);

    // ---- build x0 ----
    x0_kernel<<<NPTS/256, 256>>>(feats, pos);

    // ---- layer 1 (D=6) ----
    xsq_kernel<6><<<NPTS/256, 256>>>(x0, 6, 0);
    knn_kernel<6><<<knn_grid, 256>>>(x0, 6, 0);
    gemm_kernel<1,6><<<dim3(NEDGE/GEMM_BM, 1), 256>>>(x0, 6, 0, w1a, b1a, T,
                                                      NEDGE, 64, 12, 1);
    run_gemm_plain(T, 64, w1b, b1b, Y, NEDGE, 64, 64, 0);
    maxred_kernel<<<NPTS*64/256, 256>>>(Y, 0);

    // ---- layer 2 (D=64, input x1 = g_h[:,0:64]) ----
    xsq_kernel<64><<<NPTS/256, 256>>>(h, 192, 0);
    knn_kernel<64><<<knn_grid, 256>>>(h, 192, 0);
    gemm_kernel<1,64><<<dim3(NEDGE/GEMM_BM, 1), 256>>>(h, 192, 0, w2a, b2a, T,
                                                       NEDGE, 64, 128, 1);
    run_gemm_plain(T, 64, w2b, b2b, Y, NEDGE, 64, 64, 0);
    maxred_kernel<<<NPTS*64/256, 256>>>(Y, 64);

    // ---- layer 3 (D=64, input x2 = g_h[:,64:128]) ----
    xsq_kernel<64><<<NPTS/256, 256>>>(h, 192, 64);
    knn_kernel<64><<<knn_grid, 256>>>(h, 192, 64);
    gemm_kernel<1,64><<<dim3(NEDGE/GEMM_BM, 1), 256>>>(h, 192, 64, w3a, b3a, T,
                                                       NEDGE, 64, 128, 1);
    run_gemm_plain(T, 64, w3b, b3b, Y, NEDGE, 64, 64, 0);
    maxred_kernel<<<NPTS*64/256, 256>>>(Y, 128);

    // ---- head ----
    run_gemm_plain(h,  192,  hw1, hb1, t1, NPTS, 1024, 192, 1);
    run_gemm_plain(t1, 1024, hw2, hb2, t2, NPTS, 256, 1024, 1);
    run_gemm_plain(t2, 256,  hw3, hb3, t3, NPTS, 128, 256, 1);
    head4_kernel<<<NPTS*32/256, 256>>>(hw4, hb4, out);
}

// round 3
// speedup vs baseline: 2.4286x; 2.4286x over previous
#include <cuda_runtime.h>
#include <math.h>

#define BATCH 8
#define PTS   2048
#define NPTS  (BATCH*PTS)      // 16384
#define KNN   20
#define NEDGE (NPTS*KNN)       // 327680

typedef unsigned long long u64;

// ---------------- scratch (static device globals) ----------------
__device__ float g_x0[NPTS*6];
__device__ float g_h [NPTS*192];
__device__ float g_xsq[NPTS];
__device__ int   g_knn[NEDGE];
__device__ float g_T [NEDGE*64];
__device__ float g_Y [NEDGE*64];
__device__ float g_t1[NPTS*1024];
__device__ float g_t2[NPTS*256];
__device__ float g_t3[NPTS*128];

// ---------------- packed f32x2 helpers ----------------
__device__ __forceinline__ void ffma2(u64& acc, u64 a, u64 b) {
    asm("fma.rn.f32x2 %0, %1, %2, %0;" : "+l"(acc) : "l"(a), "l"(b));
}
__device__ __forceinline__ u64 pack2(float lo, float hi) {
    u64 r; asm("mov.b64 %0, {%1, %2};" : "=l"(r) : "f"(lo), "f"(hi)); return r;
}
__device__ __forceinline__ float2 unpack2(u64 v) {
    float2 f; asm("mov.b64 {%0, %1}, %2;" : "=f"(f.x), "=f"(f.y) : "l"(v)); return f;
}

// ---------------- build x0 = [feats | pos] ----------------
__global__ void x0_kernel(const float* __restrict__ feats, const float* __restrict__ pos) {
    int p = blockIdx.x * 256 + threadIdx.x;
    if (p >= NPTS) return;
    g_x0[p*6+0] = feats[p*3+0];
    g_x0[p*6+1] = feats[p*3+1];
    g_x0[p*6+2] = feats[p*3+2];
    g_x0[p*6+3] = pos[p*3+0];
    g_x0[p*6+4] = pos[p*3+1];
    g_x0[p*6+5] = pos[p*3+2];
}

// ---------------- squared norms ----------------
template<int D>
__global__ void xsq_kernel(const float* __restrict__ X, int stride, int off) {
    int p = blockIdx.x * 256 + threadIdx.x;
    if (p >= NPTS) return;
    float s = 0.f;
    if (D % 4 == 0) {
        #pragma unroll
        for (int f = 0; f < D; f += 4) {
            float4 v = *(const float4*)&X[(size_t)p*stride + off + f];
            s += v.x*v.x + v.y*v.y + v.z*v.z + v.w*v.w;
        }
    } else {
        #pragma unroll
        for (int f = 0; f < D; f++) {
            float v = X[(size_t)p*stride + off + f];
            s += v*v;
        }
    }
    g_xsq[p] = s;
}

// ---------------- kNN: one thread per query, register top-K ----------------
template<int D>
__global__ __launch_bounds__(128) void knn_kernel(const float* __restrict__ X,
                                                  int stride, int off) {
    const int T = 128;
    __shared__ float cf[T*D];
    __shared__ float cn[T];
    int tid = threadIdx.x;          // 128 threads
    int b   = blockIdx.y;
    int p   = b*PTS + blockIdx.x*128 + tid;

    // query features (packed pairs for D=64)
    float xi[(D == 64) ? 1 : D];
    u64   xi2[(D == 64) ? 32 : 1];
    if (D == 64) {
        #pragma unroll
        for (int q = 0; q < 32; q++) {
            float a = X[(size_t)p*stride + off + 2*q];
            float c = X[(size_t)p*stride + off + 2*q + 1];
            xi2[q] = pack2(a, c);
        }
    } else {
        #pragma unroll
        for (int f = 0; f < D; f++) xi[f] = X[(size_t)p*stride + off + f];
    }
    float xin = g_xsq[p];

    float dk[KNN]; int ik[KNN];
    #pragma unroll
    for (int k = 0; k < KNN; k++) { dk[k] = 3.4e38f; ik[k] = 0; }

    for (int t0 = 0; t0 < PTS; t0 += T) {
        int q0 = b*PTS + t0;
        __syncthreads();
        if (D == 64) {
            #pragma unroll 4
            for (int u = tid; u < T*16; u += 128) {
                int c = u >> 4, fv = u & 15;
                *(float4*)&cf[c*64 + fv*4] =
                    *(const float4*)&X[(size_t)(q0+c)*stride + off + fv*4];
            }
        } else {
            for (int u = tid; u < T*D; u += 128) {
                int c = u / D, f = u % D;
                cf[c*D + f] = X[(size_t)(q0+c)*stride + off + f];
            }
        }
        cn[tid] = g_xsq[q0 + tid];
        __syncthreads();

        for (int c = 0; c < T; c++) {
            float dot;
            if (D == 64) {
                u64 a0 = 0, a1 = 0, a2 = 0, a3 = 0;
                const ulonglong2* cp = (const ulonglong2*)&cf[c*64];
                #pragma unroll
                for (int q = 0; q < 16; q += 2) {
                    ulonglong2 v0 = cp[q];
                    ulonglong2 v1 = cp[q+1];
                    ffma2(a0, xi2[2*q],   v0.x);
                    ffma2(a1, xi2[2*q+1], v0.y);
                    ffma2(a2, xi2[2*q+2], v1.x);
                    ffma2(a3, xi2[2*q+3], v1.y);
                }
                float2 s0 = unpack2(a0), s1 = unpack2(a1);
                float2 s2 = unpack2(a2), s3 = unpack2(a3);
                dot = ((s0.x+s0.y) + (s1.x+s1.y)) + ((s2.x+s2.y) + (s3.x+s3.y));
            } else {
                dot = 0.f;
                #pragma unroll
                for (int f = 0; f < D; f++) dot += xi[f]*cf[c*D + f];
            }
            float dist = xin + cn[c] - 2.f*dot;
            if (dist < dk[KNN-1]) {
                dk[KNN-1] = dist; ik[KNN-1] = q0 + c;
                // single bubble pass, fully unrolled -> stays in registers
                #pragma unroll
                for (int k = KNN-1; k > 0; k--) {
                    if (dk[k] < dk[k-1]) {
                        float td = dk[k]; dk[k] = dk[k-1]; dk[k-1] = td;
                        int   ti = ik[k]; ik[k] = ik[k-1]; ik[k-1] = ti;
                    }
                }
            }
        }
    }
    #pragma unroll
    for (int k = 0; k < KNN; k++) g_knn[(size_t)p*KNN + k] = ik[k];
}

// ---------------- packed-f32x2 tiled GEMM: C = act(A @ W + b) ----------------
// BM=128, BN=64, BK=16, 256 threads, microtile 8 rows x 4 cols (2 f32x2)
// MODE 0: plain row-major A (Kd multiple of 16 required)
// MODE 1: gathered edge features: row r -> p=r/KNN, j=knn[r],
//         f<D -> x_p[f], f>=D -> x_j[f-D]-x_p[f-D]
#define GBM 128
#define GBN 64
#define GBK 16

template<int MODE, int D>
__global__ __launch_bounds__(256) void gemm_kernel(
        const float* __restrict__ A, int lda, int aoff,
        const float* __restrict__ W, const float* __restrict__ bias,
        float* __restrict__ C, int M, int N, int Kd, int do_relu) {
    __shared__ float As[GBK][2*GBM + 8];   // duplicated {v,v} pairs along m
    __shared__ float Ws[GBK][GBN];

    int t  = threadIdx.x;
    int m0 = blockIdx.x * GBM;
    int n0 = blockIdx.y * GBN;
    int ty = t >> 4;          // 0..15 -> rows ty*8 .. ty*8+7
    int tx = t & 15;          // 0..15 -> cols tx*4 .. tx*4+3

    u64 acc[8][2];
    #pragma unroll
    for (int i = 0; i < 8; i++) { acc[i][0] = 0ULL; acc[i][1] = 0ULL; }

    // A loader: row ar = t&127, k-slots [akb, akb+8)
    int ar  = t & 127;
    int akb = (t >> 7) * 8;
    int pidx = 0, jidx = 0;
    if (MODE == 1) { int r = m0 + ar; pidx = r / KNN; jidx = g_knn[r]; }
    const float* Ap = (MODE == 1) ? A + (size_t)pidx*lda + aoff
                                  : A + (size_t)(m0 + ar)*lda;
    const float* Aj = (MODE == 1) ? A + (size_t)jidx*lda + aoff : A;

    // W loader: 16x64 tile, 1 float4 per thread
    int wk = t >> 4;
    int wn = (t & 15) * 4;

    for (int kk = 0; kk < Kd; kk += GBK) {
        // ---- stage A (duplicated) ----
        if (MODE == 0) {
            float4 v0 = *(const float4*)&Ap[kk + akb];
            float4 v1 = *(const float4*)&Ap[kk + akb + 4];
            float v[8] = {v0.x,v0.y,v0.z,v0.w,v1.x,v1.y,v1.z,v1.w};
            #pragma unroll
            for (int c = 0; c < 8; c++)
                *(float2*)&As[akb + c][2*ar] = make_float2(v[c], v[c]);
        } else if (D == 64) {
            int fb = kk + akb;
            float v[8];
            if (fb < 64) {
                float4 v0 = *(const float4*)&Ap[fb];
                float4 v1 = *(const float4*)&Ap[fb + 4];
                v[0]=v0.x; v[1]=v0.y; v[2]=v0.z; v[3]=v0.w;
                v[4]=v1.x; v[5]=v1.y; v[6]=v1.z; v[7]=v1.w;
            } else {
                int ff = fb - 64;
                float4 j0 = *(const float4*)&Aj[ff];
                float4 j1 = *(const float4*)&Aj[ff + 4];
                float4 p0 = *(const float4*)&Ap[ff];
                float4 p1 = *(const float4*)&Ap[ff + 4];
                v[0]=j0.x-p0.x; v[1]=j0.y-p0.y; v[2]=j0.z-p0.z; v[3]=j0.w-p0.w;
                v[4]=j1.x-p1.x; v[5]=j1.y-p1.y; v[6]=j1.z-p1.z; v[7]=j1.w-p1.w;
            }
            #pragma unroll
            for (int c = 0; c < 8; c++)
                *(float2*)&As[akb + c][2*ar] = make_float2(v[c], v[c]);
        } else { // MODE 1, small D (D=6, Kd=12)
            #pragma unroll
            for (int c = 0; c < 8; c++) {
                int f = kk + akb + c;
                float v = 0.f;
                if (f < Kd) v = (f < D) ? Ap[f] : (Aj[f - D] - Ap[f - D]);
                *(float2*)&As[akb + c][2*ar] = make_float2(v, v);
            }
        }
        // ---- stage W ----
        {
            int kr = kk + wk;
            float4 wv = make_float4(0.f, 0.f, 0.f, 0.f);
            if (kr < Kd) wv = *(const float4*)&W[(size_t)kr*N + n0 + wn];
            *(float4*)&Ws[wk][wn] = wv;
        }
        __syncthreads();
        // ---- compute ----
        #pragma unroll
        for (int k = 0; k < GBK; k++) {
            u64 a2[8];
            #pragma unroll
            for (int i = 0; i < 4; i++) {
                ulonglong2 v = *(ulonglong2*)&As[k][16*ty + 4*i];
                a2[2*i]   = v.x;
                a2[2*i+1] = v.y;
            }
            ulonglong2 b2 = *(ulonglong2*)&Ws[k][tx*4];
            #pragma unroll
            for (int i = 0; i < 8; i++) {
                ffma2(acc[i][0], a2[i], b2.x);
                ffma2(acc[i][1], a2[i], b2.y);
            }
        }
        __syncthreads();
    }

    float4 bz = *(const float4*)&bias[n0 + tx*4];
    #pragma unroll
    for (int i = 0; i < 8; i++) {
        float2 v0 = unpack2(acc[i][0]);
        float2 v1 = unpack2(acc[i][1]);
        float4 o = make_float4(v0.x + bz.x, v0.y + bz.y, v1.x + bz.z, v1.y + bz.w);
        if (do_relu) {
            o.x = fmaxf(o.x, 0.f); o.y = fmaxf(o.y, 0.f);
            o.z = fmaxf(o.z, 0.f); o.w = fmaxf(o.w, 0.f);
        }
        int m = m0 + ty*8 + i;
        *(float4*)&C[(size_t)m*N + n0 + tx*4] = o;
    }
}

// ---------------- max over K neighbors -> concat buffer ----------------
__global__ void maxred_kernel(const float* __restrict__ Y, int off) {
    int t = blockIdx.x * 256 + threadIdx.x;   // NPTS*16 threads
    if (t >= NPTS*16) return;
    int p = t >> 4, c4 = (t & 15) * 4;
    float4 m = make_float4(-3.4e38f, -3.4e38f, -3.4e38f, -3.4e38f);
    #pragma unroll
    for (int k = 0; k < KNN; k++) {
        float4 v = *(const float4*)&Y[((size_t)p*KNN + k)*64 + c4];
        m.x = fmaxf(m.x, v.x); m.y = fmaxf(m.y, v.y);
        m.z = fmaxf(m.z, v.z); m.w = fmaxf(m.w, v.w);
    }
    *(float4*)&g_h[(size_t)p*192 + off + c4] = m;
}

// ---------------- head final: 128->13 + log_softmax ----------------
__global__ void head4_kernel(const float* __restrict__ W,
                             const float* __restrict__ bias,
                             float* __restrict__ out) {
    int gt   = blockIdx.x * 256 + threadIdx.x;
    int warp = gt >> 5;
    int lane = threadIdx.x & 31;
    if (warp >= NPTS) return;
    float o = -3.4e38f;
    if (lane < 13) {
        float s = bias[lane];
        #pragma unroll 8
        for (int c = 0; c < 128; c++)
            s += g_t3[(size_t)warp*128 + c] * W[c*13 + lane];
        o = s;
    }
    float m = o;
    #pragma unroll
    for (int d = 16; d; d >>= 1) m = fmaxf(m, __shfl_xor_sync(0xffffffffu, m, d));
    float e = (lane < 13) ? expf(o - m) : 0.f;
    float ssum = e;
    #pragma unroll
    for (int d = 16; d; d >>= 1) ssum += __shfl_xor_sync(0xffffffffu, ssum, d);
    if (lane < 13) out[(size_t)warp*13 + lane] = o - m - logf(ssum);
}

// ---------------- host ----------------
static inline void run_gemm_plain(const float* A, int lda, const float* W,
                                  const float* b, float* C,
                                  int M, int N, int Kd, int relu) {
    dim3 grid(M/GBM, N/GBN);
    gemm_kernel<0,0><<<grid, 256>>>(A, lda, 0, W, b, C, M, N, Kd, relu);
}

extern "C" void kernel_launch(void* const* d_in, const int* in_sizes, int n_in,
                              void* d_out, int out_size) {
    const float* feats = (const float*)d_in[0];
    const float* pos   = (const float*)d_in[1];
    const float* w1a = (const float*)d_in[3];
    const float* b1a = (const float*)d_in[4];
    const float* w1b = (const float*)d_in[5];
    const float* b1b = (const float*)d_in[6];
    const float* w2a = (const float*)d_in[7];
    const float* b2a = (const float*)d_in[8];
    const float* w2b = (const float*)d_in[9];
    const float* b2b = (const float*)d_in[10];
    const float* w3a = (const float*)d_in[11];
    const float* b3a = (const float*)d_in[12];
    const float* w3b = (const float*)d_in[13];
    const float* b3b = (const float*)d_in[14];
    const float* hw1 = (const float*)d_in[15];
    const float* hb1 = (const float*)d_in[16];
    const float* hw2 = (const float*)d_in[17];
    const float* hb2 = (const float*)d_in[18];
    const float* hw3 = (const float*)d_in[19];
    const float* hb3 = (const float*)d_in[20];
    const float* hw4 = (const float*)d_in[21];
    const float* hb4 = (const float*)d_in[22];
    float* out = (float*)d_out;

    float *x0, *h, *T, *Y, *t1, *t2, *t3;
    cudaGetSymbolAddress((void**)&x0, g_x0);
    cudaGetSymbolAddress((void**)&h,  g_h);
    cudaGetSymbolAddress((void**)&T,  g_T);
    cudaGetSymbolAddress((void**)&Y,  g_Y);
    cudaGetSymbolAddress((void**)&t1, g_t1);
    cudaGetSymbolAddress((void**)&t2, g_t2);
    cudaGetSymbolAddress((void**)&t3, g_t3);

    dim3 knn_grid(PTS/128, BATCH);

    x0_kernel<<<NPTS/256, 256>>>(feats, pos);

    // ---- layer 1 (D=6) ----
    xsq_kernel<6><<<NPTS/256, 256>>>(x0, 6, 0);
    knn_kernel<6><<<knn_grid, 128>>>(x0, 6, 0);
    gemm_kernel<1,6><<<dim3(NEDGE/GBM, 1), 256>>>(x0, 6, 0, w1a, b1a, T,
                                                  NEDGE, 64, 12, 1);
    run_gemm_plain(T, 64, w1b, b1b, Y, NEDGE, 64, 64, 0);
    maxred_kernel<<<NPTS*16/256, 256>>>(Y, 0);

    // ---- layer 2 (D=64, input x1 = g_h[:,0:64]) ----
    xsq_kernel<64><<<NPTS/256, 256>>>(h, 192, 0);
    knn_kernel<64><<<knn_grid, 128>>>(h, 192, 0);
    gemm_kernel<1,64><<<dim3(NEDGE/GBM, 1), 256>>>(h, 192, 0, w2a, b2a, T,
                                                   NEDGE, 64, 128, 1);
    run_gemm_plain(T, 64, w2b, b2b, Y, NEDGE, 64, 64, 0);
    maxred_kernel<<<NPTS*16/256, 256>>>(Y, 64);

    // ---- layer 3 (D=64, input x2 = g_h[:,64:128]) ----
    xsq_kernel<64><<<NPTS/256, 256>>>(h, 192, 64);
    knn_kernel<64><<<knn_grid, 128>>>(h, 192, 64);
    gemm_kernel<1,64><<<dim3(NEDGE/GBM, 1), 256>>>(h, 192, 64, w3a, b3a, T,
                                                   NEDGE, 64, 128, 1);
    run_gemm_plain(T, 64, w3b, b3b, Y, NEDGE, 64, 64, 0);
    maxred_kernel<<<NPTS*16/256, 256>>>(Y, 128);

    // ---- head ----
    run_gemm_plain(h,  192,  hw1, hb1, t1, NPTS, 1024, 192, 1);
    run_gemm_plain(t1, 1024, hw2, hb2, t2, NPTS, 256, 1024, 1);
    run_gemm_plain(t2, 256,  hw3, hb3, t3, NPTS, 128, 256, 1);
    head4_kernel<<<NPTS*32/256, 256>>>(hw4, hb4, out);
}

// round 4
// speedup vs baseline: 2.8177x; 1.1602x over previous
#include <cuda_runtime.h>
#include <math.h>

#define BATCH 8
#define PTS   2048
#define NPTS  (BATCH*PTS)      // 16384
#define KNN   20
#define NEDGE (NPTS*KNN)       // 327680

typedef unsigned long long u64;

// ---------------- scratch (static device globals) ----------------
__device__ __align__(16) float g_x0[NPTS*6];
__device__ __align__(16) float g_h [NPTS*192];
__device__ __align__(16) float g_xsq[NPTS];
__device__ __align__(16) int   g_knn[NEDGE];
__device__ __align__(16) float g_P [NPTS*64];
__device__ __align__(16) float g_Q [NPTS*64];
__device__ __align__(16) unsigned g_enc[NPTS*64];
__device__ __align__(16) float g_wd[64*64];
__device__ __align__(16) float g_zero[64];          // stays zero (never written)
__device__ __align__(16) float g_t1[NPTS*1024];
__device__ __align__(16) float g_t2[NPTS*256];
__device__ __align__(16) float g_t3[NPTS*128];

// ---------------- packed f32x2 helpers ----------------
__device__ __forceinline__ void ffma2(u64& acc, u64 a, u64 b) {
    asm("fma.rn.f32x2 %0, %1, %2, %0;" : "+l"(acc) : "l"(a), "l"(b));
}
__device__ __forceinline__ u64 pack2(float lo, float hi) {
    u64 r; asm("mov.b64 %0, {%1, %2};" : "=l"(r) : "f"(lo), "f"(hi)); return r;
}
__device__ __forceinline__ float2 unpack2(u64 v) {
    float2 f; asm("mov.b64 {%0, %1}, %2;" : "=f"(f.x), "=f"(f.y) : "l"(v)); return f;
}

// order-preserving float -> uint encoding (for atomicMax-based fp32 max)
__device__ __forceinline__ unsigned encf(float f) {
    unsigned u = __float_as_uint(f);
    return (u & 0x80000000u) ? ~u : (u | 0x80000000u);
}
__device__ __forceinline__ float decf(unsigned e) {
    return __uint_as_float((e & 0x80000000u) ? (e & 0x7FFFFFFFu) : ~e);
}

// ---------------- build x0 = [feats | pos] ----------------
__global__ void x0_kernel(const float* __restrict__ feats, const float* __restrict__ pos) {
    int p = blockIdx.x * 256 + threadIdx.x;
    if (p >= NPTS) return;
    g_x0[p*6+0] = feats[p*3+0];
    g_x0[p*6+1] = feats[p*3+1];
    g_x0[p*6+2] = feats[p*3+2];
    g_x0[p*6+3] = pos[p*3+0];
    g_x0[p*6+4] = pos[p*3+1];
    g_x0[p*6+5] = pos[p*3+2];
}

// ---------------- squared norms ----------------
template<int D>
__global__ void xsq_kernel(const float* __restrict__ X, int stride, int off) {
    int p = blockIdx.x * 256 + threadIdx.x;
    if (p >= NPTS) return;
    float s = 0.f;
    if (D % 4 == 0) {
        #pragma unroll
        for (int f = 0; f < D; f += 4) {
            float4 v = *(const float4*)&X[(size_t)p*stride + off + f];
            s += v.x*v.x + v.y*v.y + v.z*v.z + v.w*v.w;
        }
    } else {
        #pragma unroll
        for (int f = 0; f < D; f++) {
            float v = X[(size_t)p*stride + off + f];
            s += v*v;
        }
    }
    g_xsq[p] = s;
}

// ---------------- kNN: one thread per query, register top-K ----------------
template<int D>
__global__ __launch_bounds__(128) void knn_kernel(const float* __restrict__ X,
                                                  int stride, int off) {
    const int T = 128;
    __shared__ float cf[T*D];
    __shared__ float cn[T];
    int tid = threadIdx.x;          // 128 threads
    int b   = blockIdx.y;
    int p   = b*PTS + blockIdx.x*128 + tid;

    float xi[(D == 64) ? 1 : D];
    u64   xi2[(D == 64) ? 32 : 1];
    if (D == 64) {
        #pragma unroll
        for (int q = 0; q < 32; q++) {
            float a = X[(size_t)p*stride + off + 2*q];
            float c = X[(size_t)p*stride + off + 2*q + 1];
            xi2[q] = pack2(a, c);
        }
    } else {
        #pragma unroll
        for (int f = 0; f < D; f++) xi[f] = X[(size_t)p*stride + off + f];
    }
    float xin = g_xsq[p];

    float dk[KNN]; int ik[KNN];
    #pragma unroll
    for (int k = 0; k < KNN; k++) { dk[k] = 3.4e38f; ik[k] = 0; }

    for (int t0 = 0; t0 < PTS; t0 += T) {
        int q0 = b*PTS + t0;
        __syncthreads();
        if (D == 64) {
            #pragma unroll 4
            for (int u = tid; u < T*16; u += 128) {
                int c = u >> 4, fv = u & 15;
                *(float4*)&cf[c*64 + fv*4] =
                    *(const float4*)&X[(size_t)(q0+c)*stride + off + fv*4];
            }
        } else {
            for (int u = tid; u < T*D; u += 128) {
                int c = u / D, f = u % D;
                cf[c*D + f] = X[(size_t)(q0+c)*stride + off + f];
            }
        }
        cn[tid] = g_xsq[q0 + tid];
        __syncthreads();

        for (int c = 0; c < T; c++) {
            float dot;
            if (D == 64) {
                u64 a0 = 0, a1 = 0, a2 = 0, a3 = 0;
                const ulonglong2* cp = (const ulonglong2*)&cf[c*64];
                #pragma unroll
                for (int q = 0; q < 16; q += 2) {
                    ulonglong2 v0 = cp[q];
                    ulonglong2 v1 = cp[q+1];
                    ffma2(a0, xi2[2*q],   v0.x);
                    ffma2(a1, xi2[2*q+1], v0.y);
                    ffma2(a2, xi2[2*q+2], v1.x);
                    ffma2(a3, xi2[2*q+3], v1.y);
                }
                float2 s0 = unpack2(a0), s1 = unpack2(a1);
                float2 s2 = unpack2(a2), s3 = unpack2(a3);
                dot = ((s0.x+s0.y) + (s1.x+s1.y)) + ((s2.x+s2.y) + (s3.x+s3.y));
            } else {
                dot = 0.f;
                #pragma unroll
                for (int f = 0; f < D; f++) dot += xi[f]*cf[c*D + f];
            }
            float dist = xin + cn[c] - 2.f*dot;
            if (dist < dk[KNN-1]) {
                dk[KNN-1] = dist; ik[KNN-1] = q0 + c;
                #pragma unroll
                for (int k = KNN-1; k > 0; k--) {
                    if (dk[k] < dk[k-1]) {
                        float td = dk[k]; dk[k] = dk[k-1]; dk[k-1] = td;
                        int   ti = ik[k]; ik[k] = ik[k-1]; ik[k-1] = ti;
                    }
                }
            }
        }
    }
    #pragma unroll
    for (int k = 0; k < KNN; k++) g_knn[(size_t)p*KNN + k] = ik[k];
}

// ---------------- Wd = Wtop - Wbot  (D x 64) ----------------
__global__ void wprep_kernel(const float* __restrict__ W, int D) {
    int t = blockIdx.x * 256 + threadIdx.x;
    if (t >= D*64) return;
    g_wd[t] = W[t] - W[D*64 + t];
}

// ---------------- layer-1 P/Q (K=6, tiny) ----------------
__global__ void pq6_kernel(const float* __restrict__ w1a, const float* __restrict__ b1a) {
    int t = blockIdx.x * 256 + threadIdx.x;
    if (t >= NPTS*16) return;
    int p = t >> 4, c4 = (t & 15) * 4;
    float x[6];
    #pragma unroll
    for (int f = 0; f < 6; f++) x[f] = g_x0[p*6 + f];
    const float* Wb = w1a + 6*64;
    float4 P = *(const float4*)&b1a[c4];
    float4 Q = make_float4(0.f, 0.f, 0.f, 0.f);
    #pragma unroll
    for (int f = 0; f < 6; f++) {
        float4 wd = *(const float4*)&g_wd[f*64 + c4];
        float4 wb = *(const float4*)&Wb[f*64 + c4];
        P.x += x[f]*wd.x; P.y += x[f]*wd.y; P.z += x[f]*wd.z; P.w += x[f]*wd.w;
        Q.x += x[f]*wb.x; Q.y += x[f]*wb.y; Q.z += x[f]*wb.z; Q.w += x[f]*wb.w;
    }
    *(float4*)&g_P[p*64 + c4] = P;
    *(float4*)&g_Q[p*64 + c4] = Q;
}

// ---------------- reset / decode for encoded max buffer ----------------
__global__ void reset_kernel() {
    int t = blockIdx.x * 256 + threadIdx.x;
    if (t < NPTS*64) g_enc[t] = 0u;
}
__global__ void decode_kernel(const float* __restrict__ bias, int off) {
    int t = blockIdx.x * 256 + threadIdx.x;
    if (t >= NPTS*64) return;
    int p = t >> 6, c = t & 63;
    g_h[(size_t)p*192 + off + c] = decf(g_enc[t]) + bias[c];
}

// ---------------- packed-f32x2 tiled GEMM: C = act(A @ W + b) ----------------
#define GBM 128
#define GBN 64
#define GBK 16

__global__ __launch_bounds__(256) void gemm_kernel(
        const float* __restrict__ A, int lda, int aoff,
        const float* __restrict__ W, const float* __restrict__ bias,
        float* __restrict__ C, int M, int N, int Kd, int do_relu) {
    __shared__ float As[GBK][2*GBM + 8];
    __shared__ float Ws[GBK][GBN];

    int t  = threadIdx.x;
    int m0 = blockIdx.x * GBM;
    int n0 = blockIdx.y * GBN;
    int ty = t >> 4;
    int tx = t & 15;

    u64 acc[8][2];
    #pragma unroll
    for (int i = 0; i < 8; i++) { acc[i][0] = 0ULL; acc[i][1] = 0ULL; }

    int ar  = t & 127;
    int akb = (t >> 7) * 8;
    const float* Ap = A + (size_t)(m0 + ar)*lda + aoff;

    int wk = t >> 4;
    int wn = (t & 15) * 4;

    for (int kk = 0; kk < Kd; kk += GBK) {
        float4 v0 = *(const float4*)&Ap[kk + akb];
        float4 v1 = *(const float4*)&Ap[kk + akb + 4];
        float v[8] = {v0.x,v0.y,v0.z,v0.w,v1.x,v1.y,v1.z,v1.w};
        #pragma unroll
        for (int c = 0; c < 8; c++)
            *(float2*)&As[akb + c][2*ar] = make_float2(v[c], v[c]);
        {
            int kr = kk + wk;
            float4 wv = make_float4(0.f, 0.f, 0.f, 0.f);
            if (kr < Kd) wv = *(const float4*)&W[(size_t)kr*N + n0 + wn];
            *(float4*)&Ws[wk][wn] = wv;
        }
        __syncthreads();
        #pragma unroll
        for (int k = 0; k < GBK; k++) {
            u64 a2[8];
            #pragma unroll
            for (int i = 0; i < 4; i++) {
                ulonglong2 v2 = *(ulonglong2*)&As[k][16*ty + 4*i];
                a2[2*i]   = v2.x;
                a2[2*i+1] = v2.y;
            }
            ulonglong2 b2 = *(ulonglong2*)&Ws[k][tx*4];
            #pragma unroll
            for (int i = 0; i < 8; i++) {
                ffma2(acc[i][0], a2[i], b2.x);
                ffma2(acc[i][1], a2[i], b2.y);
            }
        }
        __syncthreads();
    }

    float4 bz = *(const float4*)&bias[n0 + tx*4];
    #pragma unroll
    for (int i = 0; i < 8; i++) {
        float2 v0 = unpack2(acc[i][0]);
        float2 v1 = unpack2(acc[i][1]);
        float4 o = make_float4(v0.x + bz.x, v0.y + bz.y, v1.x + bz.z, v1.y + bz.w);
        if (do_relu) {
            o.x = fmaxf(o.x, 0.f); o.y = fmaxf(o.y, 0.f);
            o.z = fmaxf(o.z, 0.f); o.w = fmaxf(o.w, 0.f);
        }
        int m = m0 + ty*8 + i;
        *(float4*)&C[(size_t)m*N + n0 + tx*4] = o;
    }
}

// ---------------- fused edge kernel ----------------
// rows = edges; A row r: H = relu(P[r/20] + Q[knn[r]]); out = H @ W2 (64x64);
// epilogue: per-point max via atomicMax on encoded floats.
__global__ __launch_bounds__(256) void edge_kernel(const float* __restrict__ W2) {
    __shared__ float As[GBK][2*GBM + 8];
    __shared__ float Ws[GBK][GBN];

    int t  = threadIdx.x;
    int m0 = blockIdx.x * GBM;
    int ty = t >> 4;
    int tx = t & 15;

    u64 acc[8][2];
    #pragma unroll
    for (int i = 0; i < 8; i++) { acc[i][0] = 0ULL; acc[i][1] = 0ULL; }

    int ar  = t & 127;
    int akb = (t >> 7) * 8;
    int r   = m0 + ar;
    const float* Pp = g_P + (size_t)(r / KNN) * 64;
    const float* Qj = g_Q + (size_t)g_knn[r] * 64;

    int wk = t >> 4;
    int wn = (t & 15) * 4;

    #pragma unroll
    for (int kk = 0; kk < 64; kk += GBK) {
        int fb = kk + akb;
        float4 p0 = *(const float4*)&Pp[fb];
        float4 p1 = *(const float4*)&Pp[fb + 4];
        float4 q0 = *(const float4*)&Qj[fb];
        float4 q1 = *(const float4*)&Qj[fb + 4];
        float v[8];
        v[0] = fmaxf(p0.x + q0.x, 0.f); v[1] = fmaxf(p0.y + q0.y, 0.f);
        v[2] = fmaxf(p0.z + q0.z, 0.f); v[3] = fmaxf(p0.w + q0.w, 0.f);
        v[4] = fmaxf(p1.x + q1.x, 0.f); v[5] = fmaxf(p1.y + q1.y, 0.f);
        v[6] = fmaxf(p1.z + q1.z, 0.f); v[7] = fmaxf(p1.w + q1.w, 0.f);
        #pragma unroll
        for (int c = 0; c < 8; c++)
            *(float2*)&As[akb + c][2*ar] = make_float2(v[c], v[c]);
        {
            int kr = kk + wk;
            float4 wv = *(const float4*)&W2[(size_t)kr*64 + wn];
            *(float4*)&Ws[wk][wn] = wv;
        }
        __syncthreads();
        #pragma unroll
        for (int k = 0; k < GBK; k++) {
            u64 a2[8];
            #pragma unroll
            for (int i = 0; i < 4; i++) {
                ulonglong2 v2 = *(ulonglong2*)&As[k][16*ty + 4*i];
                a2[2*i]   = v2.x;
                a2[2*i+1] = v2.y;
            }
            ulonglong2 b2 = *(ulonglong2*)&Ws[k][tx*4];
            #pragma unroll
            for (int i = 0; i < 8; i++) {
                ffma2(acc[i][0], a2[i], b2.x);
                ffma2(acc[i][1], a2[i], b2.y);
            }
        }
        __syncthreads();
    }

    // epilogue: per-point running max over the 8 rows, flush via atomicMax
    int mb   = m0 + ty*8;
    int curp = mb / KNN;
    float4 mx = make_float4(-3.4e38f, -3.4e38f, -3.4e38f, -3.4e38f);
    #pragma unroll
    for (int i = 0; i < 8; i++) {
        float2 v0 = unpack2(acc[i][0]);
        float2 v1 = unpack2(acc[i][1]);
        int p = (mb + i) / KNN;
        if (p != curp) {
            atomicMax(&g_enc[curp*64 + tx*4 + 0], encf(mx.x));
            atomicMax(&g_enc[curp*64 + tx*4 + 1], encf(mx.y));
            atomicMax(&g_enc[curp*64 + tx*4 + 2], encf(mx.z));
            atomicMax(&g_enc[curp*64 + tx*4 + 3], encf(mx.w));
            curp = p;
            mx = make_float4(-3.4e38f, -3.4e38f, -3.4e38f, -3.4e38f);
        }
        mx.x = fmaxf(mx.x, v0.x); mx.y = fmaxf(mx.y, v0.y);
        mx.z = fmaxf(mx.z, v1.x); mx.w = fmaxf(mx.w, v1.y);
    }
    atomicMax(&g_enc[curp*64 + tx*4 + 0], encf(mx.x));
    atomicMax(&g_enc[curp*64 + tx*4 + 1], encf(mx.y));
    atomicMax(&g_enc[curp*64 + tx*4 + 2], encf(mx.z));
    atomicMax(&g_enc[curp*64 + tx*4 + 3], encf(mx.w));
}

// ---------------- head final: 128->13 + log_softmax ----------------
__global__ void head4_kernel(const float* __restrict__ W,
                             const float* __restrict__ bias,
                             float* __restrict__ out) {
    int gt   = blockIdx.x * 256 + threadIdx.x;
    int warp = gt >> 5;
    int lane = threadIdx.x & 31;
    if (warp >= NPTS) return;
    float o = -3.4e38f;
    if (lane < 13) {
        float s = bias[lane];
        #pragma unroll 8
        for (int c = 0; c < 128; c++)
            s += g_t3[(size_t)warp*128 + c] * W[c*13 + lane];
        o = s;
    }
    float m = o;
    #pragma unroll
    for (int d = 16; d; d >>= 1) m = fmaxf(m, __shfl_xor_sync(0xffffffffu, m, d));
    float e = (lane < 13) ? expf(o - m) : 0.f;
    float ssum = e;
    #pragma unroll
    for (int d = 16; d; d >>= 1) ssum += __shfl_xor_sync(0xffffffffu, ssum, d);
    if (lane < 13) out[(size_t)warp*13 + lane] = o - m - logf(ssum);
}

// ---------------- host ----------------
static inline void run_gemm(const float* A, int lda, int aoff, const float* W,
                            const float* b, float* C, int M, int N, int Kd, int relu) {
    dim3 grid(M/GBM, N/GBN);
    gemm_kernel<<<grid, 256>>>(A, lda, aoff, W, b, C, M, N, Kd, relu);
}

extern "C" void kernel_launch(void* const* d_in, const int* in_sizes, int n_in,
                              void* d_out, int out_size) {
    const float* feats = (const float*)d_in[0];
    const float* pos   = (const float*)d_in[1];
    const float* w1a = (const float*)d_in[3];
    const float* b1a = (const float*)d_in[4];
    const float* w1b = (const float*)d_in[5];
    const float* b1b = (const float*)d_in[6];
    const float* w2a = (const float*)d_in[7];
    const float* b2a = (const float*)d_in[8];
    const float* w2b = (const float*)d_in[9];
    const float* b2b = (const float*)d_in[10];
    const float* w3a = (const float*)d_in[11];
    const float* b3a = (const float*)d_in[12];
    const float* w3b = (const float*)d_in[13];
    const float* b3b = (const float*)d_in[14];
    const float* hw1 = (const float*)d_in[15];
    const float* hb1 = (const float*)d_in[16];
    const float* hw2 = (const float*)d_in[17];
    const float* hb2 = (const float*)d_in[18];
    const float* hw3 = (const float*)d_in[19];
    const float* hb3 = (const float*)d_in[20];
    const float* hw4 = (const float*)d_in[21];
    const float* hb4 = (const float*)d_in[22];
    float* out = (float*)d_out;

    float *x0, *h, *P, *Q, *t1, *t2, *t3, *zero;
    cudaGetSymbolAddress((void**)&x0, g_x0);
    cudaGetSymbolAddress((void**)&h,  g_h);
    cudaGetSymbolAddress((void**)&P,  g_P);
    cudaGetSymbolAddress((void**)&Q,  g_Q);
    cudaGetSymbolAddress((void**)&t1, g_t1);
    cudaGetSymbolAddress((void**)&t2, g_t2);
    cudaGetSymbolAddress((void**)&t3, g_t3);
    cudaGetSymbolAddress((void**)&zero, g_zero);
    float* wd; cudaGetSymbolAddress((void**)&wd, g_wd);

    dim3 knn_grid(PTS/128, BATCH);
    int rg = NPTS*64/256;          // reset/decode grid

    x0_kernel<<<NPTS/256, 256>>>(feats, pos);

    // ---- layer 1 (D=6) ----
    xsq_kernel<6><<<NPTS/256, 256>>>(x0, 6, 0);
    knn_kernel<6><<<knn_grid, 128>>>(x0, 6, 0);
    wprep_kernel<<<2, 256>>>(w1a, 6);
    pq6_kernel<<<NPTS*16/256, 256>>>(w1a, b1a);
    reset_kernel<<<rg, 256>>>();
    edge_kernel<<<NEDGE/GBM, 256>>>(w1b);
    decode_kernel<<<rg, 256>>>(b1b, 0);

    // ---- layer 2 (D=64, input = g_h[:,0:64]) ----
    xsq_kernel<64><<<NPTS/256, 256>>>(h, 192, 0);
    knn_kernel<64><<<knn_grid, 128>>>(h, 192, 0);
    wprep_kernel<<<16, 256>>>(w2a, 64);
    run_gemm(h, 192, 0,  wd,          b2a,  P, NPTS, 64, 64, 0);
    run_gemm(h, 192, 0,  w2a + 64*64, zero, Q, NPTS, 64, 64, 0);
    reset_kernel<<<rg, 256>>>();
    edge_kernel<<<NEDGE/GBM, 256>>>(w2b);
    decode_kernel<<<rg, 256>>>(b2b, 64);

    // ---- layer 3 (D=64, input = g_h[:,64:128]) ----
    xsq_kernel<64><<<NPTS/256, 256>>>(h, 192, 64);
    knn_kernel<64><<<knn_grid, 128>>>(h, 192, 64);
    wprep_kernel<<<16, 256>>>(w3a, 64);
    run_gemm(h, 192, 64, wd,          b3a,  P, NPTS, 64, 64, 0);
    run_gemm(h, 192, 64, w3a + 64*64, zero, Q, NPTS, 64, 64, 0);
    reset_kernel<<<rg, 256>>>();
    edge_kernel<<<NEDGE/GBM, 256>>>(w3b);
    decode_kernel<<<rg, 256>>>(b3b, 128);

    // ---- head ----
    run_gemm(h,  192,  0, hw1, hb1, t1, NPTS, 1024, 192, 1);
    run_gemm(t1, 1024, 0, hw2, hb2, t2, NPTS, 256, 1024, 1);
    run_gemm(t2, 256,  0, hw3, hb3, t3, NPTS, 128, 256, 1);
    head4_kernel<<<NPTS*32/256, 256>>>(hw4, hb4, out);
}

// round 5
// speedup vs baseline: 3.0089x; 1.0679x over previous
#include <cuda_runtime.h>
#include <math.h>

#define BATCH 8
#define PTS   2048
#define NPTS  (BATCH*PTS)      // 16384
#define KNN   20
#define NEDGE (NPTS*KNN)       // 327680

typedef unsigned long long u64;

// ---------------- scratch ----------------
__device__ __align__(16) float g_x0[NPTS*6];
__device__ __align__(16) float g_h [NPTS*192];
__device__ __align__(16) float g_xsq[NPTS];
__device__ __align__(16) int   g_knn[NEDGE];
__device__ __align__(16) float g_PQ[NPTS*128];     // P | Q interleaved per point
__device__ __align__(16) unsigned g_enc[NPTS*64];
__device__ __align__(16) float g_wd[6*64];         // layer-1 Wtop-Wbot
__device__ __align__(16) float g_wpq[64*128];      // [Wtop-Wbot | Wbot]
__device__ __align__(16) float g_bpq[128];         // [bias | 0]
__device__ __align__(16) float g_t1[NPTS*1024];
__device__ __align__(16) float g_t2[NPTS*256];
__device__ __align__(16) float g_t3[NPTS*128];

// ---------------- packed f32x2 helpers ----------------
__device__ __forceinline__ void ffma2(u64& acc, u64 a, u64 b) {
    asm("fma.rn.f32x2 %0, %1, %2, %0;" : "+l"(acc) : "l"(a), "l"(b));
}
__device__ __forceinline__ u64 pack2(float lo, float hi) {
    u64 r; asm("mov.b64 %0, {%1, %2};" : "=l"(r) : "f"(lo), "f"(hi)); return r;
}
__device__ __forceinline__ float2 unpack2(u64 v) {
    float2 f; asm("mov.b64 {%0, %1}, %2;" : "=f"(f.x), "=f"(f.y) : "l"(v)); return f;
}
__device__ __forceinline__ unsigned encf(float f) {
    unsigned u = __float_as_uint(f);
    return (u & 0x80000000u) ? ~u : (u | 0x80000000u);
}
__device__ __forceinline__ float decf(unsigned e) {
    return __uint_as_float((e & 0x80000000u) ? (e & 0x7FFFFFFFu) : ~e);
}

// ---------------- build x0 ----------------
__global__ void x0_kernel(const float* __restrict__ feats, const float* __restrict__ pos) {
    int p = blockIdx.x * 256 + threadIdx.x;
    if (p >= NPTS) return;
    g_x0[p*6+0] = feats[p*3+0];
    g_x0[p*6+1] = feats[p*3+1];
    g_x0[p*6+2] = feats[p*3+2];
    g_x0[p*6+3] = pos[p*3+0];
    g_x0[p*6+4] = pos[p*3+1];
    g_x0[p*6+5] = pos[p*3+2];
}

// ---------------- squared norms ----------------
template<int D>
__global__ void xsq_kernel(const float* __restrict__ X, int stride, int off) {
    int p = blockIdx.x * 256 + threadIdx.x;
    if (p >= NPTS) return;
    float s = 0.f;
    if (D % 4 == 0) {
        #pragma unroll
        for (int f = 0; f < D; f += 4) {
            float4 v = *(const float4*)&X[(size_t)p*stride + off + f];
            s += v.x*v.x + v.y*v.y + v.z*v.z + v.w*v.w;
        }
    } else {
        #pragma unroll
        for (int f = 0; f < D; f++) {
            float v = X[(size_t)p*stride + off + f];
            s += v*v;
        }
    }
    g_xsq[p] = s;
}

// ---------------- kNN ----------------
template<int D>
__global__ __launch_bounds__(128) void knn_kernel(const float* __restrict__ X,
                                                  int stride, int off) {
    const int T = 128;
    __shared__ float cf[T*D];
    __shared__ float cn[T];
    int tid = threadIdx.x;
    int b   = blockIdx.y;
    int p   = b*PTS + blockIdx.x*128 + tid;

    float xi[(D == 64) ? 1 : D];
    u64   xi2[(D == 64) ? 32 : 1];
    if (D == 64) {
        #pragma unroll
        for (int q = 0; q < 32; q++) {
            float a = X[(size_t)p*stride + off + 2*q];
            float c = X[(size_t)p*stride + off + 2*q + 1];
            xi2[q] = pack2(a, c);
        }
    } else {
        #pragma unroll
        for (int f = 0; f < D; f++) xi[f] = X[(size_t)p*stride + off + f];
    }
    float xin = g_xsq[p];

    float dk[KNN]; int ik[KNN];
    #pragma unroll
    for (int k = 0; k < KNN; k++) { dk[k] = 3.4e38f; ik[k] = 0; }

    for (int t0 = 0; t0 < PTS; t0 += T) {
        int q0 = b*PTS + t0;
        __syncthreads();
        if (D == 64) {
            #pragma unroll 4
            for (int u = tid; u < T*16; u += 128) {
                int c = u >> 4, fv = u & 15;
                *(float4*)&cf[c*64 + fv*4] =
                    *(const float4*)&X[(size_t)(q0+c)*stride + off + fv*4];
            }
        } else {
            for (int u = tid; u < T*D; u += 128) {
                int c = u / D, f = u % D;
                cf[c*D + f] = X[(size_t)(q0+c)*stride + off + f];
            }
        }
        cn[tid] = g_xsq[q0 + tid];
        __syncthreads();

        for (int c = 0; c < T; c++) {
            float dot;
            if (D == 64) {
                u64 a0 = 0, a1 = 0, a2 = 0, a3 = 0;
                const ulonglong2* cp = (const ulonglong2*)&cf[c*64];
                #pragma unroll
                for (int q = 0; q < 16; q += 2) {
                    ulonglong2 v0 = cp[q];
                    ulonglong2 v1 = cp[q+1];
                    ffma2(a0, xi2[2*q],   v0.x);
                    ffma2(a1, xi2[2*q+1], v0.y);
                    ffma2(a2, xi2[2*q+2], v1.x);
                    ffma2(a3, xi2[2*q+3], v1.y);
                }
                float2 s0 = unpack2(a0), s1 = unpack2(a1);
                float2 s2 = unpack2(a2), s3 = unpack2(a3);
                dot = ((s0.x+s0.y) + (s1.x+s1.y)) + ((s2.x+s2.y) + (s3.x+s3.y));
            } else {
                dot = 0.f;
                #pragma unroll
                for (int f = 0; f < D; f++) dot += xi[f]*cf[c*D + f];
            }
            float dist = xin + cn[c] - 2.f*dot;
            if (dist < dk[KNN-1]) {
                dk[KNN-1] = dist; ik[KNN-1] = q0 + c;
                #pragma unroll
                for (int k = KNN-1; k > 0; k--) {
                    if (dk[k] < dk[k-1]) {
                        float td = dk[k]; dk[k] = dk[k-1]; dk[k-1] = td;
                        int   ti = ik[k]; ik[k] = ik[k-1]; ik[k-1] = ti;
                    }
                }
            }
        }
    }
    #pragma unroll
    for (int k = 0; k < KNN; k++) g_knn[(size_t)p*KNN + k] = ik[k];
}

// ---------------- weight prep ----------------
__global__ void wprep6_kernel(const float* __restrict__ W) {
    int t = blockIdx.x * 256 + threadIdx.x;
    if (t >= 6*64) return;
    g_wd[t] = W[t] - W[6*64 + t];
}
__global__ void wprep2_kernel(const float* __restrict__ W, const float* __restrict__ b) {
    int t = blockIdx.x * 256 + threadIdx.x;
    if (t < 64*64) {
        int f = t >> 6, c = t & 63;
        float top = W[f*64 + c], bot = W[(64+f)*64 + c];
        g_wpq[f*128 + c]      = top - bot;
        g_wpq[f*128 + 64 + c] = bot;
    }
    if (t < 128) g_bpq[t] = (t < 64) ? b[t] : 0.f;
}

// ---------------- layer-1 P/Q (D=6) -> g_PQ ----------------
__global__ void pq6_kernel(const float* __restrict__ w1a, const float* __restrict__ b1a) {
    int t = blockIdx.x * 256 + threadIdx.x;
    if (t >= NPTS*16) return;
    int p = t >> 4, c4 = (t & 15) * 4;
    float x[6];
    #pragma unroll
    for (int f = 0; f < 6; f++) x[f] = g_x0[p*6 + f];
    const float* Wb = w1a + 6*64;
    float4 P = *(const float4*)&b1a[c4];
    float4 Q = make_float4(0.f, 0.f, 0.f, 0.f);
    #pragma unroll
    for (int f = 0; f < 6; f++) {
        float4 wd = *(const float4*)&g_wd[f*64 + c4];
        float4 wb = *(const float4*)&Wb[f*64 + c4];
        P.x += x[f]*wd.x; P.y += x[f]*wd.y; P.z += x[f]*wd.z; P.w += x[f]*wd.w;
        Q.x += x[f]*wb.x; Q.y += x[f]*wb.y; Q.z += x[f]*wb.z; Q.w += x[f]*wb.w;
    }
    *(float4*)&g_PQ[p*128 + c4]      = P;
    *(float4*)&g_PQ[p*128 + 64 + c4] = Q;
}

// ---------------- reset / decode ----------------
__global__ void reset_kernel() {
    int t = blockIdx.x * 256 + threadIdx.x;
    if (t < NPTS*64) g_enc[t] = 0u;
}
__global__ void decode_kernel(const float* __restrict__ bias, int off) {
    int t = blockIdx.x * 256 + threadIdx.x;
    if (t >= NPTS*64) return;
    int p = t >> 6, c = t & 63;
    g_h[(size_t)p*192 + off + c] = decf(g_enc[t]) + bias[c];
}

// ---------------- GEMM core: block 128x64, 128 threads, 8x8 microtile ----------------
// A pairs packed along M (As[k][m], float2 = 2 adjacent rows); B scalar + reg-dup.
#define GBM 128
#define GBN 64
#define GBK 16

struct AccBlk { u64 a[4][8]; };

__device__ __forceinline__ void mt_compute(AccBlk& A_, const float As[GBK][GBM+4],
                                           const float Ws[GBK][GBN], int ty, int tx) {
    #pragma unroll
    for (int k = 0; k < GBK; k++) {
        ulonglong2 aA = *(const ulonglong2*)&As[k][ty*8];
        ulonglong2 aB = *(const ulonglong2*)&As[k][ty*8 + 4];
        u64 am[4] = {aA.x, aA.y, aB.x, aB.y};
        float4 w0 = *(const float4*)&Ws[k][tx*8];
        float4 w1 = *(const float4*)&Ws[k][tx*8 + 4];
        u64 wp[8];
        wp[0] = pack2(w0.x, w0.x); wp[1] = pack2(w0.y, w0.y);
        wp[2] = pack2(w0.z, w0.z); wp[3] = pack2(w0.w, w0.w);
        wp[4] = pack2(w1.x, w1.x); wp[5] = pack2(w1.y, w1.y);
        wp[6] = pack2(w1.z, w1.z); wp[7] = pack2(w1.w, w1.w);
        #pragma unroll
        for (int i = 0; i < 4; i++)
            #pragma unroll
            for (int j = 0; j < 8; j++)
                ffma2(A_.a[i][j], am[i], wp[j]);
    }
}

__global__ __launch_bounds__(128) void gemm_kernel(
        const float* __restrict__ A, int lda, int aoff,
        const float* __restrict__ W, const float* __restrict__ bias,
        float* __restrict__ C, int M, int N, int Kd, int do_relu) {
    __shared__ float As[GBK][GBM+4];
    __shared__ float Ws[GBK][GBN];

    int t  = threadIdx.x;
    int m0 = blockIdx.x * GBM;
    int n0 = blockIdx.y * GBN;
    int ty = t >> 3, tx = t & 7;

    AccBlk acc;
    #pragma unroll
    for (int i = 0; i < 4; i++)
        #pragma unroll
        for (int j = 0; j < 8; j++) acc.a[i][j] = 0ULL;

    const float* Ap = A + (size_t)(m0 + t)*lda + aoff;
    int wk = t >> 3, wn = (t & 7) * 8;

    for (int kk = 0; kk < Kd; kk += GBK) {
        float4 a0 = *(const float4*)&Ap[kk];
        float4 a1 = *(const float4*)&Ap[kk + 4];
        float4 a2 = *(const float4*)&Ap[kk + 8];
        float4 a3 = *(const float4*)&Ap[kk + 12];
        const float* Wr = &W[(size_t)(kk + wk)*N + n0 + wn];
        float4 w0 = *(const float4*)Wr;
        float4 w1 = *(const float4*)(Wr + 4);
        __syncthreads();
        As[0][t]=a0.x;  As[1][t]=a0.y;  As[2][t]=a0.z;  As[3][t]=a0.w;
        As[4][t]=a1.x;  As[5][t]=a1.y;  As[6][t]=a1.z;  As[7][t]=a1.w;
        As[8][t]=a2.x;  As[9][t]=a2.y;  As[10][t]=a2.z; As[11][t]=a2.w;
        As[12][t]=a3.x; As[13][t]=a3.y; As[14][t]=a3.z; As[15][t]=a3.w;
        *(float4*)&Ws[wk][wn]     = w0;
        *(float4*)&Ws[wk][wn + 4] = w1;
        __syncthreads();
        mt_compute(acc, As, Ws, ty, tx);
    }

    float4 bz0 = *(const float4*)&bias[n0 + tx*8];
    float4 bz1 = *(const float4*)&bias[n0 + tx*8 + 4];
    #pragma unroll
    for (int i = 0; i < 4; i++) {
        float lo[8], hi[8];
        #pragma unroll
        for (int j = 0; j < 8; j++) {
            float2 v = unpack2(acc.a[i][j]);
            lo[j] = v.x; hi[j] = v.y;
        }
        float bb[8] = {bz0.x,bz0.y,bz0.z,bz0.w,bz1.x,bz1.y,bz1.z,bz1.w};
        #pragma unroll
        for (int j = 0; j < 8; j++) {
            lo[j] += bb[j]; hi[j] += bb[j];
            if (do_relu) { lo[j] = fmaxf(lo[j], 0.f); hi[j] = fmaxf(hi[j], 0.f); }
        }
        int m = m0 + ty*8 + 2*i;
        float* Cr0 = &C[(size_t)m*N + n0 + tx*8];
        float* Cr1 = Cr0 + N;
        *(float4*)Cr0       = make_float4(lo[0],lo[1],lo[2],lo[3]);
        *(float4*)(Cr0 + 4) = make_float4(lo[4],lo[5],lo[6],lo[7]);
        *(float4*)Cr1       = make_float4(hi[0],hi[1],hi[2],hi[3]);
        *(float4*)(Cr1 + 4) = make_float4(hi[4],hi[5],hi[6],hi[7]);
    }
}

// ---------------- fused edge kernel: H=relu(P[p]+Q[j]); out=H@W2; max->atomicMax ----------------
__global__ __launch_bounds__(128) void edge_kernel(const float* __restrict__ W2) {
    __shared__ float As[GBK][GBM+4];
    __shared__ float Ws[GBK][GBN];

    int t  = threadIdx.x;
    int m0 = blockIdx.x * GBM;
    int ty = t >> 3, tx = t & 7;

    AccBlk acc;
    #pragma unroll
    for (int i = 0; i < 4; i++)
        #pragma unroll
        for (int j = 0; j < 8; j++) acc.a[i][j] = 0ULL;

    int r = m0 + t;
    const float* Pp = g_PQ + (size_t)(r / KNN) * 128;
    const float* Qj = g_PQ + (size_t)g_knn[r] * 128 + 64;
    int wk = t >> 3, wn = (t & 7) * 8;

    #pragma unroll
    for (int kk = 0; kk < 64; kk += GBK) {
        float4 p0 = *(const float4*)&Pp[kk];
        float4 p1 = *(const float4*)&Pp[kk + 4];
        float4 p2 = *(const float4*)&Pp[kk + 8];
        float4 p3 = *(const float4*)&Pp[kk + 12];
        float4 q0 = *(const float4*)&Qj[kk];
        float4 q1 = *(const float4*)&Qj[kk + 4];
        float4 q2 = *(const float4*)&Qj[kk + 8];
        float4 q3 = *(const float4*)&Qj[kk + 12];
        const float* Wr = &W2[(size_t)(kk + wk)*64 + wn];
        float4 w0 = *(const float4*)Wr;
        float4 w1 = *(const float4*)(Wr + 4);
        __syncthreads();
        As[0][t]=fmaxf(p0.x+q0.x,0.f);  As[1][t]=fmaxf(p0.y+q0.y,0.f);
        As[2][t]=fmaxf(p0.z+q0.z,0.f);  As[3][t]=fmaxf(p0.w+q0.w,0.f);
        As[4][t]=fmaxf(p1.x+q1.x,0.f);  As[5][t]=fmaxf(p1.y+q1.y,0.f);
        As[6][t]=fmaxf(p1.z+q1.z,0.f);  As[7][t]=fmaxf(p1.w+q1.w,0.f);
        As[8][t]=fmaxf(p2.x+q2.x,0.f);  As[9][t]=fmaxf(p2.y+q2.y,0.f);
        As[10][t]=fmaxf(p2.z+q2.z,0.f); As[11][t]=fmaxf(p2.w+q2.w,0.f);
        As[12][t]=fmaxf(p3.x+q3.x,0.f); As[13][t]=fmaxf(p3.y+q3.y,0.f);
        As[14][t]=fmaxf(p3.z+q3.z,0.f); As[15][t]=fmaxf(p3.w+q3.w,0.f);
        *(float4*)&Ws[wk][wn]     = w0;
        *(float4*)&Ws[wk][wn + 4] = w1;
        __syncthreads();
        mt_compute(acc, As, Ws, ty, tx);
    }

    // per-point max epilogue over this thread's 8 consecutive edge rows
    int mb = m0 + ty*8;
    int curp = mb / KNN;
    float mx[8];
    #pragma unroll
    for (int j = 0; j < 8; j++) mx[j] = -3.4e38f;
    #pragma unroll
    for (int i = 0; i < 4; i++) {
        #pragma unroll
        for (int half = 0; half < 2; half++) {
            int rr = mb + 2*i + half;
            int pp = rr / KNN;
            if (pp != curp) {
                #pragma unroll
                for (int j = 0; j < 8; j++)
                    atomicMax(&g_enc[curp*64 + tx*8 + j], encf(mx[j]));
                curp = pp;
                #pragma unroll
                for (int j = 0; j < 8; j++) mx[j] = -3.4e38f;
            }
            #pragma unroll
            for (int j = 0; j < 8; j++) {
                float2 v = unpack2(acc.a[i][j]);
                float val = half ? v.y : v.x;
                mx[j] = fmaxf(mx[j], val);
            }
        }
    }
    #pragma unroll
    for (int j = 0; j < 8; j++)
        atomicMax(&g_enc[curp*64 + tx*8 + j], encf(mx[j]));
}

// ---------------- head final: 128->13 + log_softmax ----------------
__global__ void head4_kernel(const float* __restrict__ W,
                             const float* __restrict__ bias,
                             float* __restrict__ out) {
    int gt   = blockIdx.x * 256 + threadIdx.x;
    int warp = gt >> 5;
    int lane = threadIdx.x & 31;
    if (warp >= NPTS) return;
    float o = -3.4e38f;
    if (lane < 13) {
        float s = bias[lane];
        #pragma unroll 8
        for (int c = 0; c < 128; c++)
            s += g_t3[(size_t)warp*128 + c] * W[c*13 + lane];
        o = s;
    }
    float m = o;
    #pragma unroll
    for (int d = 16; d; d >>= 1) m = fmaxf(m, __shfl_xor_sync(0xffffffffu, m, d));
    float e = (lane < 13) ? expf(o - m) : 0.f;
    float ssum = e;
    #pragma unroll
    for (int d = 16; d; d >>= 1) ssum += __shfl_xor_sync(0xffffffffu, ssum, d);
    if (lane < 13) out[(size_t)warp*13 + lane] = o - m - logf(ssum);
}

// ---------------- host ----------------
static inline void run_gemm(const float* A, int lda, int aoff, const float* W,
                            const float* b, float* C, int M, int N, int Kd, int relu) {
    dim3 grid(M/GBM, N/GBN);
    gemm_kernel<<<grid, 128>>>(A, lda, aoff, W, b, C, M, N, Kd, relu);
}

extern "C" void kernel_launch(void* const* d_in, const int* in_sizes, int n_in,
                              void* d_out, int out_size) {
    const float* feats = (const float*)d_in[0];
    const float* pos   = (const float*)d_in[1];
    const float* w1a = (const float*)d_in[3];
    const float* b1a = (const float*)d_in[4];
    const float* w1b = (const float*)d_in[5];
    const float* b1b = (const float*)d_in[6];
    const float* w2a = (const float*)d_in[7];
    const float* b2a = (const float*)d_in[8];
    const float* w2b = (const float*)d_in[9];
    const float* b2b = (const float*)d_in[10];
    const float* w3a = (const float*)d_in[11];
    const float* b3a = (const float*)d_in[12];
    const float* w3b = (const float*)d_in[13];
    const float* b3b = (const float*)d_in[14];
    const float* hw1 = (const float*)d_in[15];
    const float* hb1 = (const float*)d_in[16];
    const float* hw2 = (const float*)d_in[17];
    const float* hb2 = (const float*)d_in[18];
    const float* hw3 = (const float*)d_in[19];
    const float* hb3 = (const float*)d_in[20];
    const float* hw4 = (const float*)d_in[21];
    const float* hb4 = (const float*)d_in[22];
    float* out = (float*)d_out;

    float *x0, *h, *PQ, *t1, *t2, *t3, *wpq, *bpq;
    cudaGetSymbolAddress((void**)&x0, g_x0);
    cudaGetSymbolAddress((void**)&h,  g_h);
    cudaGetSymbolAddress((void**)&PQ, g_PQ);
    cudaGetSymbolAddress((void**)&t1, g_t1);
    cudaGetSymbolAddress((void**)&t2, g_t2);
    cudaGetSymbolAddress((void**)&t3, g_t3);
    cudaGetSymbolAddress((void**)&wpq, g_wpq);
    cudaGetSymbolAddress((void**)&bpq, g_bpq);

    dim3 knn_grid(PTS/128, BATCH);
    int rg = NPTS*64/256;

    x0_kernel<<<NPTS/256, 256>>>(feats, pos);

    // ---- layer 1 (D=6) ----
    xsq_kernel<6><<<NPTS/256, 256>>>(x0, 6, 0);
    knn_kernel<6><<<knn_grid, 128>>>(x0, 6, 0);
    wprep6_kernel<<<2, 256>>>(w1a);
    pq6_kernel<<<NPTS*16/256, 256>>>(w1a, b1a);
    reset_kernel<<<rg, 256>>>();
    edge_kernel<<<NEDGE/GBM, 128>>>(w1b);
    decode_kernel<<<rg, 256>>>(b1b, 0);

    // ---- layer 2 ----
    xsq_kernel<64><<<NPTS/256, 256>>>(h, 192, 0);
    knn_kernel<64><<<knn_grid, 128>>>(h, 192, 0);
    wprep2_kernel<<<16, 256>>>(w2a, b2a);
    run_gemm(h, 192, 0, wpq, bpq, PQ, NPTS, 128, 64, 0);
    reset_kernel<<<rg, 256>>>();
    edge_kernel<<<NEDGE/GBM, 128>>>(w2b);
    decode_kernel<<<rg, 256>>>(b2b, 64);

    // ---- layer 3 ----
    xsq_kernel<64><<<NPTS/256, 256>>>(h, 192, 64);
    knn_kernel<64><<<knn_grid, 128>>>(h, 192, 64);
    wprep2_kernel<<<16, 256>>>(w3a, b3a);
    run_gemm(h, 192, 64, wpq, bpq, PQ, NPTS, 128, 64, 0);
    reset_kernel<<<rg, 256>>>();
    edge_kernel<<<NEDGE/GBM, 128>>>(w3b);
    decode_kernel<<<rg, 256>>>(b3b, 128);

    // ---- head ----
    run_gemm(h,  192,  0, hw1, hb1, t1, NPTS, 1024, 192, 1);
    run_gemm(t1, 1024, 0, hw2, hb2, t2, NPTS, 256, 1024, 1);
    run_gemm(t2, 256,  0, hw3, hb3, t3, NPTS, 128, 256, 1);
    head4_kernel<<<NPTS*32/256, 256>>>(hw4, hb4, out);
}